// round 6
// baseline (speedup 1.0000x reference)
#include <cuda_runtime.h>
#include <cuda_fp16.h>
#include <math_constants.h>

#define HH 512
#define WW 512
#define BB 16
// window p=35, pad=17, chunk=35
// loss = mean(erosion_35x35(min_c x)) - 1   (erosion = separable min filter)

// Intermediate: vertically eroded field, [B, H, W] as half (packed half2 pairs along W)
__device__ __align__(16) __half2 g_t2[BB * HH * WW / 2];
// Per-block partial sums from kernel 2 (1024 blocks)
__device__ float g_partial[1024];
// Completion counter for fused final reduction (reset each run)
__device__ int g_count;

// ---------------------------------------------------------------------------
// Kernel 1: channel-min of x (fp32 -> fp16) fused with vertical min-filter,
// van Herk chunk 35, half2 packed along W. Single S array (no spill).
// Block = (32 lanes, 4 chunks) = 128 thr; tile = 64 W cols x 174 rows (22KB).
// grid = (W/64, B, 4)
// ---------------------------------------------------------------------------
__global__ __launch_bounds__(128) void k1_vert(const float* __restrict__ x) {
    __shared__ __half2 sm[174 * 32];

    const int tx  = threadIdx.x;
    const int ty  = threadIdx.y;
    const int tid = ty * 32 + tx;
    const int wc0 = blockIdx.x * 64;
    const int b   = blockIdx.y;
    const int z   = blockIdx.z;
    const int r0  = z * 140;                 // 4 chunks * 35 rows per z-group
    const float INF = CUDART_INF_F;

    // Load channel-min into smem rows [r0-17, r0+157), as half2 (2 W cols)
    const float* xb = x + (size_t)b * 3 * HH * WW;
    for (int j = tid; j < 174 * 16; j += 128) {
        int r  = j >> 4;
        int c4 = j & 15;                      // float4 slot within 64 cols
        int gh = r0 - 17 + r;
        float4 m;
        if ((unsigned)gh < HH) {
            const float4* p = (const float4*)(xb + (size_t)gh * WW + wc0 + c4 * 4);
            float4 a0 = p[0];
            float4 a1 = p[(HH * WW) / 4];
            float4 a2 = p[(2 * HH * WW) / 4];
            m.x = fminf(a0.x, fminf(a1.x, a2.x));
            m.y = fminf(a0.y, fminf(a1.y, a2.y));
            m.z = fminf(a0.z, fminf(a1.z, a2.z));
            m.w = fminf(a0.w, fminf(a1.w, a2.w));
        } else {
            m = make_float4(INF, INF, INF, INF);
        }
        sm[r * 32 + c4 * 2]     = __floats2half2_rn(m.x, m.y);
        sm[r * 32 + c4 * 2 + 1] = __floats2half2_rn(m.z, m.w);
    }
    __syncthreads();

    const int c    = z * 4 + ty;              // chunk index
    const int base = 35 * c;                  // first output row of chunk
    if (base >= HH) return;
    const int lb = 35 * ty + 17;              // smem row of 'base'
    const __half2 HINF = __float2half2_rn(CUDART_INF_F);

    // Pass 1: suffix minima
    __half2 S[35];
    __half2 run = HINF;
    #pragma unroll
    for (int k = 0; k < 52; k++) {
        if (k == 35) run = HINF;
        run = __hmin2(run, sm[(lb + 34 - k) * 32 + tx]);
        if (k >= 17) S[51 - k] = run;
    }

    // Pass 2: prefix minima, combine + store on the fly
    run = HINF;
    const size_t ob = (size_t)b * HH;
    const int wcol = (wc0 >> 1) + tx;
    #pragma unroll
    for (int k = 0; k < 52; k++) {
        if (k == 35) run = HINF;
        run = __hmin2(run, sm[(lb + k) * 32 + tx]);
        if (k >= 17) {
            int i = base + k - 17;
            if (i < HH)
                g_t2[(ob + i) * (WW / 2) + wcol] = __hmin2(S[k - 17], run);
        }
    }
}

// ---------------------------------------------------------------------------
// Kernel 2: horizontal min-filter, ROLE-SPLIT van Herk: each chain handled by
// TWO threads (suffix role / prefix role), results staged in smem, combine
// split across both. No register arrays -> no spill; 2x thread count.
// half2 packs two image rows; smem tile transposed [w-slot][row-pair].
// Block = 128 thr = 32 row-pair lanes x 2 chunks x 2 roles; covers
// 64 rows x 70 output cols. grid = (H/64, B, 8). 1024 blocks.
// ---------------------------------------------------------------------------
__global__ __launch_bounds__(128) void k2_horiz(float* __restrict__ out) {
    __shared__ __half2 smh2[106 * 33];        // tile: 106 w-slots x 32 row-pairs (14KB)
    __shared__ __half2 Ssm[35 * 66];          // [j][chain] suffix minima (9.2KB)
    __shared__ __half2 Psm[35 * 66];          // [j][chain] prefix minima (9.2KB)
    __shared__ float red[128];
    __shared__ int isLast;

    const int tx   = threadIdx.x;             // row-pair lane (0..31)
    const int ty   = threadIdx.y;             // 0..3
    const int tid  = ty * 32 + tx;
    const int cidx = ty & 1;                  // chunk slot within block
    const int role = ty >> 1;                 // 0 = suffix, 1 = prefix
    const int h0   = blockIdx.x * 64;
    const int b    = blockIdx.y;
    const int z    = blockIdx.z;              // 2 chunks per z
    const __half2 HINF2 = __float2half2_rn(CUDART_INF_F);

    // Load tile: w slots [70z-18, 70z+88) x 64 rows, transposed into smem.
    // 32 row-pairs x 53 half2-pair slots = 1696 loads.
    {
        const int pbase = 35 * z - 9;         // first half2 column index
        for (int j = tid; j < 1696; j += 128) {
            int rp = j / 53;                  // row-pair
            int tp = j - rp * 53;             // tile half2-pair slot
            int pc = pbase + tp;              // global half2 column
            __half2 a = HINF2, c = HINF2;
            if ((unsigned)pc < (WW / 2)) {
                size_t o = ((size_t)(b * HH + h0 + 2 * rp)) * (WW / 2) + pc;
                a = g_t2[o];                  // row 2rp   : (w, w+1)
                c = g_t2[o + WW / 2];         // row 2rp+1 : (w, w+1)
            }
            smh2[(2 * tp) * 33 + rp]     = __lows2half2(a, c);
            smh2[(2 * tp + 1) * 33 + rp] = __highs2half2(a, c);
        }
    }
    __syncthreads();

    // Phase 1: one 52-step chain per thread, results to smem. chain = cidx*32+tx.
    const int chain = cidx * 32 + tx;
    const int lb    = cidx * 35 + 18;         // tile slot of chunk's first output col
    if (role == 0) {
        __half2 rs = HINF2;
        #pragma unroll
        for (int k = 0; k < 52; k++) {
            if (k == 35) rs = HINF2;
            rs = __hmin2(rs, smh2[(lb + 34 - k) * 33 + tx]);
            if (k >= 17) Ssm[(51 - k) * 66 + chain] = rs;
        }
    } else {
        __half2 rp = HINF2;
        #pragma unroll
        for (int k = 0; k < 52; k++) {
            if (k == 35) rp = HINF2;
            rp = __hmin2(rp, smh2[(lb + k) * 33 + tx]);
            if (k >= 17) Psm[(k - 17) * 66 + chain] = rp;
        }
    }
    __syncthreads();

    // Phase 2: combine + accumulate. role 0 -> j 0..17, role 1 -> j 18..34.
    const int basew = 35 * (z * 2 + cidx);
    __half2 hacc = __float2half2_rn(0.0f);
    #pragma unroll
    for (int u = 0; u < 18; u++) {
        int j = role * 18 + u;
        if (j < 35 && basew + j < WW)
            hacc = __hadd2(hacc, __hmin2(Ssm[j * 66 + chain], Psm[j * 66 + chain]));
    }
    float2 e = __half22float2(hacc);
    float acc = e.x + e.y;

    // Deterministic in-block reduction (128 threads)
    red[tid] = acc;
    __syncthreads();
    #pragma unroll
    for (int s = 64; s > 0; s >>= 1) {
        if (tid < s) red[tid] += red[tid + s];
        __syncthreads();
    }
    if (tid == 0) {
        g_partial[b * 64 + z * 8 + blockIdx.x] = red[0];
        __threadfence();
        int done = atomicAdd(&g_count, 1);
        isLast = (done == 1023) ? 1 : 0;
    }
    __syncthreads();

    // Last block: deterministic final reduction over the 1024 partials
    if (isLast) {
        float v = 0.0f;
        #pragma unroll
        for (int i = 0; i < 8; i++) v += g_partial[tid + i * 128];
        red[tid] = v;
        __syncthreads();
        #pragma unroll
        for (int s = 64; s > 0; s >>= 1) {
            if (tid < s) red[tid] += red[tid + s];
            __syncthreads();
        }
        if (tid == 0) {
            out[0] = red[0] * (1.0f / 4194304.0f) - 1.0f;
            g_count = 0;   // reset for next graph replay
        }
    }
}

extern "C" void kernel_launch(void* const* d_in, const int* in_sizes, int n_in,
                              void* d_out, int out_size) {
    const float* x = (const float*)d_in[0];
    float* out = (float*)d_out;

    k1_vert<<<dim3(WW / 64, BB, 4), dim3(32, 4)>>>(x);
    k2_horiz<<<dim3(HH / 64, BB, 8), dim3(32, 4)>>>(out);
}

// round 7
// speedup vs baseline: 1.4225x; 1.4225x over previous
#include <cuda_runtime.h>
#include <cuda_fp16.h>
#include <math_constants.h>

#define HH 512
#define WW 512
#define BB 16
// window p=35, pad=17, chunk=35
// loss = mean(erosion_35x35(min_c x)) - 1   (erosion = separable min filter)

// Intermediate: vertically eroded field, [B, H, W] as half (packed half2 pairs along W)
__device__ __align__(16) __half2 g_t2[BB * HH * WW / 2];
// Per-block partial sums from kernel 2 (512 blocks)
__device__ float g_partial[512];
// Completion counter for fused final reduction (reset each run)
__device__ int g_count;

// ---------------------------------------------------------------------------
// Kernel 1 (UNCHANGED round-4 form — measured at the memory roofline):
// channel-min of x (fp32 -> fp16) fused with vertical min-filter,
// van Herk chunk 35, half2 packed along W.
// Block = (32 lanes, 4 chunks) = 128 thr; grid = (W/64, B, 4).
// ---------------------------------------------------------------------------
__global__ __launch_bounds__(128) void k1_vert(const float* __restrict__ x) {
    __shared__ __half2 sm[174 * 32];

    const int tx  = threadIdx.x;
    const int ty  = threadIdx.y;
    const int tid = ty * 32 + tx;
    const int wc0 = blockIdx.x * 64;
    const int b   = blockIdx.y;
    const int z   = blockIdx.z;
    const int r0  = z * 140;                 // 4 chunks * 35 rows per z-group
    const float INF = CUDART_INF_F;

    // Load channel-min into smem rows [r0-17, r0+157), as half2 (2 W cols)
    const float* xb = x + (size_t)b * 3 * HH * WW;
    for (int j = tid; j < 174 * 16; j += 128) {
        int r  = j >> 4;
        int c4 = j & 15;                      // float4 slot within 64 cols
        int gh = r0 - 17 + r;
        float4 m;
        if ((unsigned)gh < HH) {
            const float4* p = (const float4*)(xb + (size_t)gh * WW + wc0 + c4 * 4);
            float4 a0 = p[0];
            float4 a1 = p[(HH * WW) / 4];
            float4 a2 = p[(2 * HH * WW) / 4];
            m.x = fminf(a0.x, fminf(a1.x, a2.x));
            m.y = fminf(a0.y, fminf(a1.y, a2.y));
            m.z = fminf(a0.z, fminf(a1.z, a2.z));
            m.w = fminf(a0.w, fminf(a1.w, a2.w));
        } else {
            m = make_float4(INF, INF, INF, INF);
        }
        sm[r * 32 + c4 * 2]     = __floats2half2_rn(m.x, m.y);
        sm[r * 32 + c4 * 2 + 1] = __floats2half2_rn(m.z, m.w);
    }
    __syncthreads();

    const int c    = z * 4 + ty;              // chunk index
    const int base = 35 * c;                  // first output row of chunk
    if (base >= HH) return;
    const int lb = 35 * ty + 17;              // smem row of 'base'
    const __half2 HINF = __float2half2_rn(CUDART_INF_F);

    // Pass 1: suffix minima
    __half2 S[35];
    __half2 run = HINF;
    #pragma unroll
    for (int k = 0; k < 52; k++) {
        if (k == 35) run = HINF;
        run = __hmin2(run, sm[(lb + 34 - k) * 32 + tx]);
        if (k >= 17) S[51 - k] = run;
    }

    // Pass 2: prefix minima, combine + store on the fly
    run = HINF;
    const size_t ob = (size_t)b * HH;
    const int wcol = (wc0 >> 1) + tx;
    #pragma unroll
    for (int k = 0; k < 52; k++) {
        if (k == 35) run = HINF;
        run = __hmin2(run, sm[(lb + k) * 32 + tx]);
        if (k >= 17) {
            int i = base + k - 17;
            if (i < HH)
                g_t2[(ob + i) * (WW / 2) + wcol] = __hmin2(S[k - 17], run);
        }
    }
}

// ---------------------------------------------------------------------------
// Kernel 2: horizontal min-filter, transposed half2-row-pair tile (round-4
// structure) + EVEN/ODD SPLIT CHAINS (2x ILP, critical path halved, no big
// register arrays beyond S) + dual half2 accumulators.
// Block = (32 row-pair lanes, 4 w-chunks) = 128 thr; covers 64 rows x 140
// cols. grid = (H/64, B, 4) = 512 blocks. Reg ceiling 128 (occ is
// grid-limited, so registers are free).
// ---------------------------------------------------------------------------
__global__ __launch_bounds__(128, 4) void k2_horiz(float* __restrict__ out) {
    __shared__ __half2 smh2[176 * 33];        // [tile w-slot][row-pair], 23.2KB
    __shared__ float red[128];
    __shared__ int isLast;

    const int tx  = threadIdx.x;              // row-pair lane
    const int ty  = threadIdx.y;              // w-chunk within block
    const int tid = ty * 32 + tx;
    const int h0  = blockIdx.x * 64;
    const int b   = blockIdx.y;
    const int z   = blockIdx.z;
    const __half2 HINF2 = __float2half2_rn(CUDART_INF_F);

    // Load tile: w slots [w0-18, w0+158) x 64 rows, transposed into smem.
    {
        const int pbase = 70 * z - 9;         // first half2-pair column index
        #pragma unroll
        for (int i = 0; i < 22; i++) {
            int j  = tid + i * 128;
            int rp = j / 88;                  // row-pair
            int tp = j - rp * 88;             // tile half2-pair slot
            int pc = pbase + tp;              // global half2 column
            __half2 a = HINF2, c = HINF2;
            if ((unsigned)pc < (WW / 2)) {
                size_t o = ((size_t)(b * HH + h0 + 2 * rp)) * (WW / 2) + pc;
                a = g_t2[o];                  // row 2rp   : (w, w+1)
                c = g_t2[o + WW / 2];         // row 2rp+1 : (w, w+1)
            }
            // repack to (row even, row odd) per w column
            smh2[(2 * tp) * 33 + rp]     = __lows2half2(a, c);
            smh2[(2 * tp + 1) * 33 + rp] = __highs2half2(a, c);
        }
    }
    __syncthreads();

    float acc = 0.0f;
    const int chunk = z * 4 + ty;
    const int basew = 35 * chunk;             // first output col of chunk
    if (basew < WW) {
        const int lb = 35 * ty + 18;          // tile slot of 'basew'

        // Pass 1: suffix minima via two independent stride-2 chains.
        // Both chains reset at the segment boundary (k==35).
        __half2 S[35];
        __half2 se = HINF2, so = HINF2;
        #pragma unroll
        for (int k = 0; k < 52; k++) {
            if (k == 35) { se = HINF2; so = HINF2; }
            __half2 v = smh2[(lb + 34 - k) * 33 + tx];
            if (k & 1) so = __hmin2(so, v); else se = __hmin2(se, v);
            if (k >= 17) S[51 - k] = __hmin2(se, so);
        }

        // Pass 2: prefix minima via split chains, combine + accumulate on
        // the fly with two interleaved half2 accumulators.
        __half2 pe = HINF2, po = HINF2;
        __half2 a0 = __float2half2_rn(0.0f);
        __half2 a1 = __float2half2_rn(0.0f);
        #pragma unroll
        for (int k = 0; k < 52; k++) {
            if (k == 35) { pe = HINF2; po = HINF2; }
            __half2 v = smh2[(lb + k) * 33 + tx];
            if (k & 1) po = __hmin2(po, v); else pe = __hmin2(pe, v);
            if (k >= 17) {
                int iw = basew + k - 17;
                if (iw < WW) {
                    __half2 e = __hmin2(S[k - 17], __hmin2(pe, po));
                    if (k & 1) a1 = __hadd2(a1, e); else a0 = __hadd2(a0, e);
                }
            }
        }
        float2 e2 = __half22float2(__hadd2(a0, a1));
        acc = e2.x + e2.y;
    }

    // Deterministic in-block reduction (128 threads)
    red[tid] = acc;
    __syncthreads();
    #pragma unroll
    for (int s = 64; s > 0; s >>= 1) {
        if (tid < s) red[tid] += red[tid + s];
        __syncthreads();
    }
    if (tid == 0) {
        g_partial[b * 32 + z * 8 + blockIdx.x] = red[0];
        __threadfence();
        int done = atomicAdd(&g_count, 1);
        isLast = (done == 511) ? 1 : 0;
    }
    __syncthreads();

    // Last block: deterministic final reduction over the 512 partials
    if (isLast) {
        float v = g_partial[tid] + g_partial[tid + 128] +
                  g_partial[tid + 256] + g_partial[tid + 384];
        red[tid] = v;
        __syncthreads();
        #pragma unroll
        for (int s = 64; s > 0; s >>= 1) {
            if (tid < s) red[tid] += red[tid + s];
            __syncthreads();
        }
        if (tid == 0) {
            out[0] = red[0] * (1.0f / 4194304.0f) - 1.0f;
            g_count = 0;   // reset for next graph replay
        }
    }
}

extern "C" void kernel_launch(void* const* d_in, const int* in_sizes, int n_in,
                              void* d_out, int out_size) {
    const float* x = (const float*)d_in[0];
    float* out = (float*)d_out;

    k1_vert<<<dim3(WW / 64, BB, 4), dim3(32, 4)>>>(x);
    k2_horiz<<<dim3(HH / 64, BB, 4), dim3(32, 4)>>>(out);
}